// round 6
// baseline (speedup 1.0000x reference)
#include <cuda_runtime.h>
#include <cuda_bf16.h>

#define NN 100000
#define EE 1200000
#define HD 64
#define NLAY 3
#define SCANB 512
#define NSCANBLK ((NN + SCANB - 1) / SCANB)   // 196

// ---------------- scratch (no allocations allowed) ----------------
__device__ __nv_bfloat162 g_P[NN * HD / 2];   // bf16 attention features
__device__ __nv_bfloat162 g_Q[NN * HD / 2];
__device__ float g_xA[NN * HD];
__device__ float g_xB[NN * HD];
__device__ float g_mask[EE];
__device__ float g_rs[NN];
// CSR build
__device__ int g_cnt[NN];          // zero at module load; re-zeroed by scan23
__device__ int g_off[NN + 1];
__device__ int g_cur[NN];
__device__ int g_ecol[EE];
__device__ int g_bsum[256];

// ---------------- f32x2 helpers (Blackwell packed FMA) ----------------
__device__ __forceinline__ unsigned long long ffma2(unsigned long long a,
                                                    unsigned long long b,
                                                    unsigned long long c) {
    unsigned long long d;
    asm("fma.rn.f32x2 %0, %1, %2, %3;" : "=l"(d) : "l"(a), "l"(b), "l"(c));
    return d;
}
__device__ __forceinline__ unsigned long long pack2(float lo, float hi) {
    unsigned long long d;
    asm("mov.b64 %0, {%1, %2};" : "=l"(d) : "f"(lo), "f"(hi));
    return d;
}
__device__ __forceinline__ float2 unpack2(unsigned long long v) {
    float2 f;
    asm("mov.b64 {%0, %1}, %2;" : "=f"(f.x), "=f"(f.y) : "l"(v));
    return f;
}

// ================= CSR build (once per call) =================
__global__ void __launch_bounds__(256) hist_k(const int* __restrict__ row) {
    int e = blockIdx.x * 256 + threadIdx.x;
    if (e < EE) atomicAdd(&g_cnt[row[e]], 1);
}

__global__ void __launch_bounds__(SCANB) scan1() {
    __shared__ int s[SCANB];
    int t = threadIdx.x;
    int i = blockIdx.x * SCANB + t;
    int v = (i < NN) ? g_cnt[i] : 0;
    s[t] = v;
    for (int o = 1; o < SCANB; o <<= 1) {
        __syncthreads();
        int x = (t >= o) ? s[t - o] : 0;
        __syncthreads();
        s[t] += x;
    }
    __syncthreads();
    if (i < NN) g_off[i] = s[t] - v;            // exclusive within block
    if (t == SCANB - 1) g_bsum[blockIdx.x] = s[t];
}

// fused: every block re-scans the 196 block sums, then finalizes offsets
__global__ void __launch_bounds__(256) scan23() {
    __shared__ int s[256];
    __shared__ int ex[256];
    int t = threadIdx.x;
    int v = (t < NSCANBLK) ? g_bsum[t] : 0;
    s[t] = v;
    for (int o = 1; o < 256; o <<= 1) {
        __syncthreads();
        int x = (t >= o) ? s[t - o] : 0;
        __syncthreads();
        s[t] += x;
    }
    __syncthreads();
    ex[t] = s[t] - v;                            // exclusive block offsets
    __syncthreads();
    int i = blockIdx.x * 256 + t;
    if (i < NN) {
        int o = g_off[i] + ex[i / SCANB];
        g_off[i] = o;
        g_cur[i] = o;
        g_cnt[i] = 0;                            // reset for next replay
    }
    if (i == 0) g_off[NN] = EE;
}

__global__ void __launch_bounds__(256) scatter_k(const int* __restrict__ row,
                                                 const int* __restrict__ col) {
    int e = blockIdx.x * 256 + threadIdx.x;
    if (e < EE) {
        int pos = atomicAdd(&g_cur[row[e]], 1);
        g_ecol[pos] = col[e];
    }
}

// ---------------- per-node fused 2-stage GEMM (f32x2 FMA, bf16 out) -------
__global__ void __launch_bounds__(256) node_gemm(
    const float* __restrict__ feat, int xsel,
    const float* __restrict__ W1n, const float* __restrict__ b1n,
    const float* __restrict__ W1s, const float* __restrict__ b1s,
    const float* __restrict__ a1W)
{
    const float* x = (xsel == 0) ? feat : (xsel == 1 ? g_xA : g_xB);
    const float* W1; const float* b1; const float* W3; __nv_bfloat162* out;
    if (blockIdx.y == 0) { W1 = W1n; b1 = b1n; W3 = a1W;        out = g_P; }
    else                 { W1 = W1s; b1 = b1s; W3 = a1W + 4096; out = g_Q; }

    __shared__ float sW1[4096];
    __shared__ float sW3[4096];
    __shared__ float sX[4096];

    int t = threadIdx.x;
    for (int i = 4 * t; i < 4096; i += 1024) {
        *(float4*)(sW1 + i) = *(const float4*)(W1 + i);
        *(float4*)(sW3 + i) = *(const float4*)(W3 + i);
    }
    int n0 = blockIdx.x * 64;
    for (int i = 4 * t; i < 4096; i += 1024) {
        int node = n0 + (i >> 6);
        float4 v = make_float4(0.f, 0.f, 0.f, 0.f);
        if (node < NN) v = *(const float4*)(x + (size_t)node * HD + (i & 63));
        *(float4*)(sX + i) = v;
    }
    __syncthreads();

    int c4 = (t & 15) * 4;
    int ns = (t >> 4) * 4;

    float4 bb = *(const float4*)(b1 + c4);
    unsigned long long a01[4], a23[4];
    {
        unsigned long long i01 = pack2(bb.x, bb.y);
        unsigned long long i23 = pack2(bb.z, bb.w);
#pragma unroll
        for (int i = 0; i < 4; i++) { a01[i] = i01; a23[i] = i23; }
    }
#pragma unroll 8
    for (int k = 0; k < 64; k++) {
        unsigned long long w01 = *(const unsigned long long*)(sW1 + k * 64 + c4);
        unsigned long long w23 = *(const unsigned long long*)(sW1 + k * 64 + c4 + 2);
#pragma unroll
        for (int i = 0; i < 4; i++) {
            float xb = sX[(ns + i) * 64 + k];
            unsigned long long xx = pack2(xb, xb);
            a01[i] = ffma2(xx, w01, a01[i]);
            a23[i] = ffma2(xx, w23, a23[i]);
        }
    }
    __syncthreads();
#pragma unroll
    for (int i = 0; i < 4; i++) {
        float2 u01 = unpack2(a01[i]);
        float2 u23 = unpack2(a23[i]);
        float4 a;
        a.x = fmaxf(u01.x, 0.f); a.y = fmaxf(u01.y, 0.f);
        a.z = fmaxf(u23.x, 0.f); a.w = fmaxf(u23.y, 0.f);
        *(float4*)(sX + (ns + i) * 64 + c4) = a;
    }
    __syncthreads();

#pragma unroll
    for (int i = 0; i < 4; i++) { a01[i] = 0ULL; a23[i] = 0ULL; }
#pragma unroll 8
    for (int k = 0; k < 64; k++) {
        unsigned long long w01 = *(const unsigned long long*)(sW3 + k * 64 + c4);
        unsigned long long w23 = *(const unsigned long long*)(sW3 + k * 64 + c4 + 2);
#pragma unroll
        for (int i = 0; i < 4; i++) {
            float ab = sX[(ns + i) * 64 + k];
            unsigned long long xx = pack2(ab, ab);
            a01[i] = ffma2(xx, w01, a01[i]);
            a23[i] = ffma2(xx, w23, a23[i]);
        }
    }
#pragma unroll
    for (int i = 0; i < 4; i++) {
        int node = n0 + ns + i;
        if (node < NN) {
            float2 u01 = unpack2(a01[i]);
            float2 u23 = unpack2(a23[i]);
            __nv_bfloat162 b0 = __float22bfloat162_rn(u01);
            __nv_bfloat162 b1v = __float22bfloat162_rn(u23);
            *(uint2*)(out + (size_t)node * 32 + (c4 >> 1)) =
                make_uint2(*(unsigned*)&b0, *(unsigned*)&b1v);
        }
    }
}

// ---------------- gate ----------------
__device__ __forceinline__ float gatef(float la) {
    float m = __fdividef(1.f, 1.f + __expf(-la));
    m = m * 1.5f - 0.45f;
    return fminf(fmaxf(m, 0.f), 1.f);
}

__device__ __forceinline__ float dot_pq(float4 p, uint2 qv, float4 w) {
    __nv_bfloat162 qa = *(__nv_bfloat162*)&qv.x;
    __nv_bfloat162 qb = *(__nv_bfloat162*)&qv.y;
    float2 q01 = __bfloat1622float2(qa);
    float2 q23 = __bfloat1622float2(qb);
    return fmaxf(p.x + q01.x, 0.f) * w.x + fmaxf(p.y + q01.y, 0.f) * w.y
         + fmaxf(p.z + q23.x, 0.f) * w.z + fmaxf(p.w + q23.y, 0.f) * w.w;
}

// ---- edge pass 1 (CSR): attention gate + rowsum -> d^{-1/2} ---------------
// 16 lanes per row; edge metadata batch-loaded per group, shfl-broadcast
__global__ void __launch_bounds__(256) edge_att_csr(
    const float* __restrict__ b1, const float* __restrict__ w2,
    const float* __restrict__ b2)
{
    int t = threadIdx.x;
    int r = blockIdx.x * 16 + (t >> 4);
    int lane = t & 15;
    unsigned gm = 0xFFFFu << (t & 16);

    int start = g_off[r], end = g_off[r + 1];
    uint2 pv = *(const uint2*)(g_P + (size_t)r * 32 + lane * 2);
    float2 p01 = __bfloat1622float2(*(__nv_bfloat162*)&pv.x);
    float2 p23 = __bfloat1622float2(*(__nv_bfloat162*)&pv.y);
    float4 bb = *(const float4*)(b1 + lane * 4);
    float4 w  = *(const float4*)(w2 + lane * 4);
    float4 p = make_float4(p01.x + bb.x, p01.y + bb.y, p23.x + bb.z, p23.y + bb.w);
    float b2v = b2[0];

    float rs = 0.f;
    for (int base = start; base < end; base += 16) {
        int nb = min(16, end - base);
        int cl = (lane < nb) ? g_ecol[base + lane] : 0;
        int j = 0;
        for (; j + 4 <= nb; j += 4) {
            int c0 = __shfl_sync(gm, cl, j + 0, 16);
            int c1 = __shfl_sync(gm, cl, j + 1, 16);
            int c2 = __shfl_sync(gm, cl, j + 2, 16);
            int c3 = __shfl_sync(gm, cl, j + 3, 16);
            uint2 q0 = *(const uint2*)(g_Q + (size_t)c0 * 32 + lane * 2);
            uint2 q1 = *(const uint2*)(g_Q + (size_t)c1 * 32 + lane * 2);
            uint2 q2 = *(const uint2*)(g_Q + (size_t)c2 * 32 + lane * 2);
            uint2 q3 = *(const uint2*)(g_Q + (size_t)c3 * 32 + lane * 2);
            float s0 = dot_pq(p, q0, w);
            float s1 = dot_pq(p, q1, w);
            float s2 = dot_pq(p, q2, w);
            float s3 = dot_pq(p, q3, w);
#pragma unroll
            for (int o = 8; o >= 1; o >>= 1) {
                s0 += __shfl_xor_sync(gm, s0, o, 16);
                s1 += __shfl_xor_sync(gm, s1, o, 16);
                s2 += __shfl_xor_sync(gm, s2, o, 16);
                s3 += __shfl_xor_sync(gm, s3, o, 16);
            }
            if (lane < 4) {        // gate evals spread over 4 lanes
                float sv = (lane == 0) ? s0 : (lane == 1) ? s1
                         : (lane == 2) ? s2 : s3;
                float m = gatef(sv + b2v);
                g_mask[base + j + lane] = m;
                rs += m;
            }
        }
        for (; j < nb; j++) {
            int c = __shfl_sync(gm, cl, j, 16);
            uint2 q = *(const uint2*)(g_Q + (size_t)c * 32 + lane * 2);
            float s = dot_pq(p, q, w);
#pragma unroll
            for (int o = 8; o >= 1; o >>= 1) s += __shfl_xor_sync(gm, s, o, 16);
            if (lane == 0) {
                float m = gatef(s + b2v);
                g_mask[base + j] = m;
                rs += m;
            }
        }
    }
    // total rowsum across the 16 lanes, then d^{-1/2} (dis_k fused here)
#pragma unroll
    for (int o = 8; o >= 1; o >>= 1) rs += __shfl_xor_sync(gm, rs, o, 16);
    if (lane == 0) g_rs[r] = fminf(rsqrtf(rs + 1e-6f), 10.f);
}

// ---- edge pass 2 (CSR): gated SpMM + out accumulation ---------------------
// edge metadata (col, mask, rs[col]) batch-loaded per group, shfl-broadcast
__global__ void __launch_bounds__(256) edge_spmm_csr(
    const float* __restrict__ feat, int xsel, int useB,
    float* __restrict__ out, int first)
{
    const float* x = (xsel == 0) ? feat : (xsel == 1 ? g_xA : g_xB);
    float* xo = useB ? g_xB : g_xA;
    int t = threadIdx.x;
    int r = blockIdx.x * 16 + (t >> 4);
    int lane = t & 15;
    unsigned gm = 0xFFFFu << (t & 16);
    int start = g_off[r], end = g_off[r + 1];

    float dr = g_rs[r];                      // clipped d^{-1/2}
    float4 acc = make_float4(0.f, 0.f, 0.f, 0.f);

    for (int base = start; base < end; base += 16) {
        int nb = min(16, end - base);
        int cl = 0; float vl = 0.f;
        if (lane < nb) {
            cl = g_ecol[base + lane];
            float ml = g_mask[base + lane];
            vl = ml * g_rs[cl];              // parallel rs gather, one per lane
        }
        int j = 0;
        for (; j + 4 <= nb; j += 4) {
            int c0 = __shfl_sync(gm, cl, j + 0, 16);
            int c1 = __shfl_sync(gm, cl, j + 1, 16);
            int c2 = __shfl_sync(gm, cl, j + 2, 16);
            int c3 = __shfl_sync(gm, cl, j + 3, 16);
            float v0 = __shfl_sync(gm, vl, j + 0, 16);
            float v1 = __shfl_sync(gm, vl, j + 1, 16);
            float v2 = __shfl_sync(gm, vl, j + 2, 16);
            float v3 = __shfl_sync(gm, vl, j + 3, 16);
            float4 x0 = *(const float4*)(x + (size_t)c0 * HD + lane * 4);
            float4 x1 = *(const float4*)(x + (size_t)c1 * HD + lane * 4);
            float4 x2 = *(const float4*)(x + (size_t)c2 * HD + lane * 4);
            float4 x3 = *(const float4*)(x + (size_t)c3 * HD + lane * 4);
            acc.x += v0 * x0.x; acc.y += v0 * x0.y; acc.z += v0 * x0.z; acc.w += v0 * x0.w;
            acc.x += v1 * x1.x; acc.y += v1 * x1.y; acc.z += v1 * x1.z; acc.w += v1 * x1.w;
            acc.x += v2 * x2.x; acc.y += v2 * x2.y; acc.z += v2 * x2.z; acc.w += v2 * x2.w;
            acc.x += v3 * x3.x; acc.y += v3 * x3.y; acc.z += v3 * x3.z; acc.w += v3 * x3.w;
        }
        for (; j < nb; j++) {
            int c = __shfl_sync(gm, cl, j, 16);
            float v = __shfl_sync(gm, vl, j, 16);
            float4 xc = *(const float4*)(x + (size_t)c * HD + lane * 4);
            acc.x += v * xc.x; acc.y += v * xc.y;
            acc.z += v * xc.z; acc.w += v * xc.w;
        }
    }
    acc.x *= dr; acc.y *= dr; acc.z *= dr; acc.w *= dr;

    size_t o4 = (size_t)r * HD + lane * 4;
    *(float4*)(xo + o4) = acc;
    float4 base4 = first ? *(const float4*)(feat + o4) : *(const float4*)(out + o4);
    base4.x += acc.x; base4.y += acc.y; base4.z += acc.z; base4.w += acc.w;
    *(float4*)(out + o4) = base4;
}

// ---------------- launch ----------------
extern "C" void kernel_launch(void* const* d_in, const int* in_sizes, int n_in,
                              void* d_out, int out_size)
{
    const float* feat = (const float*)d_in[0];
    const float* nbW  = (const float*)d_in[1];
    const float* nbb  = (const float*)d_in[2];
    const float* sW   = (const float*)d_in[3];
    const float* sb   = (const float*)d_in[4];
    const float* a1W  = (const float*)d_in[5];
    const float* a1b  = (const float*)d_in[6];
    const float* a2W  = (const float*)d_in[7];
    const float* a2b  = (const float*)d_in[8];
    const int*   row  = (const int*)d_in[9];
    const int*   col  = (const int*)d_in[10];
    float* out = (float*)d_out;

    const int ggrid = (NN + 63) / 64;      // 1563
    const int rgrid = NN / 16;             // 6250
    const int ngrid = (NN + 255) / 256;
    const int egrid = (EE + 255) / 256;

    // gemm(l0) is independent of the CSR build — launch it first
    node_gemm<<<dim3(ggrid, 2), 256>>>(feat, 0,
                                       nbW, nbb, sW, sb, a1W);
    hist_k<<<egrid, 256>>>(row);
    scan1<<<NSCANBLK, SCANB>>>();
    scan23<<<ngrid, 256>>>();
    scatter_k<<<egrid, 256>>>(row, col);

    for (int l = 0; l < NLAY; l++) {
        int xsel = (l == 0) ? 0 : ((l == 1) ? 1 : 2);
        int useB = l & 1;
        if (l > 0) {
            node_gemm<<<dim3(ggrid, 2), 256>>>(feat, xsel,
                                               nbW + l * 4096, nbb + l * 64,
                                               sW  + l * 4096, sb  + l * 64,
                                               a1W + l * 8192);
        }
        edge_att_csr<<<rgrid, 256>>>(a1b + l * 64, a2W + l * 64, a2b + l);
        edge_spmm_csr<<<rgrid, 256>>>(feat, xsel, useB, out, l == 0);
    }
}

// round 7
// speedup vs baseline: 1.0837x; 1.0837x over previous
#include <cuda_runtime.h>
#include <cuda_bf16.h>

#define NN 100000
#define EE 1200000
#define HD 64
#define NLAY 3
#define SCANB 512
#define NSCANBLK ((NN + SCANB - 1) / SCANB)   // 196

// ---------------- scratch (no allocations allowed) ----------------
__device__ __nv_bfloat162 g_P[NN * HD / 2];   // bf16 attention features
__device__ __nv_bfloat162 g_Q[NN * HD / 2];
__device__ float g_xA[NN * HD];
__device__ float g_xB[NN * HD];
__device__ float g_mask[EE];
__device__ float g_rs[NN];
// CSR build
__device__ int g_cnt[NN];          // zero at module load; re-zeroed by scan23
__device__ int g_off[NN + 1];
__device__ int g_cur[NN];
__device__ int g_ecol[EE];
__device__ int g_bsum[256];

// ---------------- f32x2 helpers (Blackwell packed FMA) ----------------
__device__ __forceinline__ unsigned long long ffma2(unsigned long long a,
                                                    unsigned long long b,
                                                    unsigned long long c) {
    unsigned long long d;
    asm("fma.rn.f32x2 %0, %1, %2, %3;" : "=l"(d) : "l"(a), "l"(b), "l"(c));
    return d;
}
__device__ __forceinline__ unsigned long long pack2(float lo, float hi) {
    unsigned long long d;
    asm("mov.b64 %0, {%1, %2};" : "=l"(d) : "f"(lo), "f"(hi));
    return d;
}
__device__ __forceinline__ float2 unpack2(unsigned long long v) {
    float2 f;
    asm("mov.b64 {%0, %1}, %2;" : "=f"(f.x), "=f"(f.y) : "l"(v));
    return f;
}

// ================= CSR build (once per call) =================
__global__ void __launch_bounds__(256) hist_k(const int* __restrict__ row) {
    int e = blockIdx.x * 256 + threadIdx.x;
    if (e < EE) atomicAdd(&g_cnt[row[e]], 1);
}

__global__ void __launch_bounds__(SCANB) scan1() {
    __shared__ int s[SCANB];
    int t = threadIdx.x;
    int i = blockIdx.x * SCANB + t;
    int v = (i < NN) ? g_cnt[i] : 0;
    s[t] = v;
    for (int o = 1; o < SCANB; o <<= 1) {
        __syncthreads();
        int x = (t >= o) ? s[t - o] : 0;
        __syncthreads();
        s[t] += x;
    }
    __syncthreads();
    if (i < NN) g_off[i] = s[t] - v;            // exclusive within block
    if (t == SCANB - 1) g_bsum[blockIdx.x] = s[t];
}

// fused: every block re-scans the 196 block sums, then finalizes offsets
__global__ void __launch_bounds__(256) scan23() {
    __shared__ int s[256];
    __shared__ int ex[256];
    int t = threadIdx.x;
    int v = (t < NSCANBLK) ? g_bsum[t] : 0;
    s[t] = v;
    for (int o = 1; o < 256; o <<= 1) {
        __syncthreads();
        int x = (t >= o) ? s[t - o] : 0;
        __syncthreads();
        s[t] += x;
    }
    __syncthreads();
    ex[t] = s[t] - v;
    __syncthreads();
    int i = blockIdx.x * 256 + t;
    if (i < NN) {
        int o = g_off[i] + ex[i / SCANB];
        g_off[i] = o;
        g_cur[i] = o;
        g_cnt[i] = 0;
    }
    if (i == 0) g_off[NN] = EE;
}

__global__ void __launch_bounds__(256) scatter_k(const int* __restrict__ row,
                                                 const int* __restrict__ col) {
    int e = blockIdx.x * 256 + threadIdx.x;
    if (e < EE) {
        int pos = atomicAdd(&g_cur[row[e]], 1);
        g_ecol[pos] = col[e];
    }
}

// ---------------- per-node fused 2-stage GEMM (f32x2 FMA, bf16 out) -------
__global__ void __launch_bounds__(256) node_gemm(
    const float* __restrict__ feat, int xsel,
    const float* __restrict__ W1n, const float* __restrict__ b1n,
    const float* __restrict__ W1s, const float* __restrict__ b1s,
    const float* __restrict__ a1W)
{
    const float* x = (xsel == 0) ? feat : (xsel == 1 ? g_xA : g_xB);
    const float* W1; const float* b1; const float* W3; __nv_bfloat162* out;
    if (blockIdx.y == 0) { W1 = W1n; b1 = b1n; W3 = a1W;        out = g_P; }
    else                 { W1 = W1s; b1 = b1s; W3 = a1W + 4096; out = g_Q; }

    __shared__ float sW1[4096];
    __shared__ float sW3[4096];
    __shared__ float sX[4096];

    int t = threadIdx.x;
    for (int i = 4 * t; i < 4096; i += 1024) {
        *(float4*)(sW1 + i) = *(const float4*)(W1 + i);
        *(float4*)(sW3 + i) = *(const float4*)(W3 + i);
    }
    int n0 = blockIdx.x * 64;
    for (int i = 4 * t; i < 4096; i += 1024) {
        int node = n0 + (i >> 6);
        float4 v = make_float4(0.f, 0.f, 0.f, 0.f);
        if (node < NN) v = *(const float4*)(x + (size_t)node * HD + (i & 63));
        *(float4*)(sX + i) = v;
    }
    __syncthreads();

    int c4 = (t & 15) * 4;
    int ns = (t >> 4) * 4;

    float4 bb = *(const float4*)(b1 + c4);
    unsigned long long a01[4], a23[4];
    {
        unsigned long long i01 = pack2(bb.x, bb.y);
        unsigned long long i23 = pack2(bb.z, bb.w);
#pragma unroll
        for (int i = 0; i < 4; i++) { a01[i] = i01; a23[i] = i23; }
    }
#pragma unroll 8
    for (int k = 0; k < 64; k++) {
        unsigned long long w01 = *(const unsigned long long*)(sW1 + k * 64 + c4);
        unsigned long long w23 = *(const unsigned long long*)(sW1 + k * 64 + c4 + 2);
#pragma unroll
        for (int i = 0; i < 4; i++) {
            float xb = sX[(ns + i) * 64 + k];
            unsigned long long xx = pack2(xb, xb);
            a01[i] = ffma2(xx, w01, a01[i]);
            a23[i] = ffma2(xx, w23, a23[i]);
        }
    }
    __syncthreads();
#pragma unroll
    for (int i = 0; i < 4; i++) {
        float2 u01 = unpack2(a01[i]);
        float2 u23 = unpack2(a23[i]);
        float4 a;
        a.x = fmaxf(u01.x, 0.f); a.y = fmaxf(u01.y, 0.f);
        a.z = fmaxf(u23.x, 0.f); a.w = fmaxf(u23.y, 0.f);
        *(float4*)(sX + (ns + i) * 64 + c4) = a;
    }
    __syncthreads();

#pragma unroll
    for (int i = 0; i < 4; i++) { a01[i] = 0ULL; a23[i] = 0ULL; }
#pragma unroll 8
    for (int k = 0; k < 64; k++) {
        unsigned long long w01 = *(const unsigned long long*)(sW3 + k * 64 + c4);
        unsigned long long w23 = *(const unsigned long long*)(sW3 + k * 64 + c4 + 2);
#pragma unroll
        for (int i = 0; i < 4; i++) {
            float ab = sX[(ns + i) * 64 + k];
            unsigned long long xx = pack2(ab, ab);
            a01[i] = ffma2(xx, w01, a01[i]);
            a23[i] = ffma2(xx, w23, a23[i]);
        }
    }
#pragma unroll
    for (int i = 0; i < 4; i++) {
        int node = n0 + ns + i;
        if (node < NN) {
            float2 u01 = unpack2(a01[i]);
            float2 u23 = unpack2(a23[i]);
            __nv_bfloat162 b0 = __float22bfloat162_rn(u01);
            __nv_bfloat162 b1v = __float22bfloat162_rn(u23);
            *(uint2*)(out + (size_t)node * 32 + (c4 >> 1)) =
                make_uint2(*(unsigned*)&b0, *(unsigned*)&b1v);
        }
    }
}

// ---------------- gate ----------------
__device__ __forceinline__ float gatef(float la) {
    float m = __fdividef(1.f, 1.f + __expf(-la));
    m = m * 1.5f - 0.45f;
    return fminf(fmaxf(m, 0.f), 1.f);
}

__device__ __forceinline__ float dot_pq(float4 p, uint2 qv, float4 w) {
    __nv_bfloat162 qa = *(__nv_bfloat162*)&qv.x;
    __nv_bfloat162 qb = *(__nv_bfloat162*)&qv.y;
    float2 q01 = __bfloat1622float2(qa);
    float2 q23 = __bfloat1622float2(qb);
    return fmaxf(p.x + q01.x, 0.f) * w.x + fmaxf(p.y + q01.y, 0.f) * w.y
         + fmaxf(p.z + q23.x, 0.f) * w.z + fmaxf(p.w + q23.y, 0.f) * w.w;
}

// ---- edge pass 1 (CSR): attention gate + rowsum -> d^{-1/2} ---------------
// R5 structure: direct (uniform/broadcast) metadata loads, 4-way unroll
__global__ void __launch_bounds__(256) edge_att_csr(
    const float* __restrict__ b1, const float* __restrict__ w2,
    const float* __restrict__ b2)
{
    int t = threadIdx.x;
    int r = blockIdx.x * 16 + (t >> 4);
    int lane = t & 15;
    unsigned gm = 0xFFFFu << (t & 16);

    int start = g_off[r], end = g_off[r + 1];
    uint2 pv = *(const uint2*)(g_P + (size_t)r * 32 + lane * 2);
    float2 p01 = __bfloat1622float2(*(__nv_bfloat162*)&pv.x);
    float2 p23 = __bfloat1622float2(*(__nv_bfloat162*)&pv.y);
    float4 bb = *(const float4*)(b1 + lane * 4);
    float4 w  = *(const float4*)(w2 + lane * 4);
    float4 p = make_float4(p01.x + bb.x, p01.y + bb.y, p23.x + bb.z, p23.y + bb.w);
    float b2v = b2[0];

    float rs = 0.f;
    int j = start;
    for (; j + 4 <= end; j += 4) {
        int c0 = g_ecol[j + 0], c1 = g_ecol[j + 1];
        int c2 = g_ecol[j + 2], c3 = g_ecol[j + 3];
        uint2 q0 = *(const uint2*)(g_Q + (size_t)c0 * 32 + lane * 2);
        uint2 q1 = *(const uint2*)(g_Q + (size_t)c1 * 32 + lane * 2);
        uint2 q2 = *(const uint2*)(g_Q + (size_t)c2 * 32 + lane * 2);
        uint2 q3 = *(const uint2*)(g_Q + (size_t)c3 * 32 + lane * 2);
        float s0 = dot_pq(p, q0, w);
        float s1 = dot_pq(p, q1, w);
        float s2 = dot_pq(p, q2, w);
        float s3 = dot_pq(p, q3, w);
#pragma unroll
        for (int o = 8; o >= 1; o >>= 1) {
            s0 += __shfl_xor_sync(gm, s0, o, 16);
            s1 += __shfl_xor_sync(gm, s1, o, 16);
            s2 += __shfl_xor_sync(gm, s2, o, 16);
            s3 += __shfl_xor_sync(gm, s3, o, 16);
        }
        if (lane < 4) {        // gate evals spread over 4 lanes (s* valid on all)
            float sv = (lane == 0) ? s0 : (lane == 1) ? s1
                     : (lane == 2) ? s2 : s3;
            float m = gatef(sv + b2v);
            g_mask[j + lane] = m;
            rs += m;
        }
    }
    for (; j < end; j++) {
        int c = g_ecol[j];
        uint2 q = *(const uint2*)(g_Q + (size_t)c * 32 + lane * 2);
        float s = dot_pq(p, q, w);
#pragma unroll
        for (int o = 8; o >= 1; o >>= 1) s += __shfl_xor_sync(gm, s, o, 16);
        if (lane == 0) {
            float m = gatef(s + b2v);
            g_mask[j] = m;
            rs += m;
        }
    }
    // total rowsum across the 16 lanes, then d^{-1/2} (dis_k fused)
#pragma unroll
    for (int o = 8; o >= 1; o >>= 1) rs += __shfl_xor_sync(gm, rs, o, 16);
    if (lane == 0) g_rs[r] = fminf(rsqrtf(rs + 1e-6f), 10.f);
}

// ---- edge pass 2 (CSR): gated SpMM + out accumulation, 8-way unroll -------
// R5 structure: direct (uniform/broadcast) metadata loads
__global__ void __launch_bounds__(256) edge_spmm_csr(
    const float* __restrict__ feat, int xsel, int useB,
    float* __restrict__ out, int first)
{
    const float* x = (xsel == 0) ? feat : (xsel == 1 ? g_xA : g_xB);
    float* xo = useB ? g_xB : g_xA;
    int t = threadIdx.x;
    int r = blockIdx.x * 16 + (t >> 4);
    int lane = t & 15;
    int start = g_off[r], end = g_off[r + 1];

    float dr = g_rs[r];                      // clipped d^{-1/2}
    float4 acc = make_float4(0.f, 0.f, 0.f, 0.f);

    int j = start;
    for (; j + 8 <= end; j += 8) {
        int   c[8]; float vv[8]; float4 xt[8];
#pragma unroll
        for (int u = 0; u < 8; u++) c[u] = g_ecol[j + u];
#pragma unroll
        for (int u = 0; u < 8; u++) vv[u] = g_mask[j + u] * g_rs[c[u]];
#pragma unroll
        for (int u = 0; u < 8; u++)
            xt[u] = *(const float4*)(x + (size_t)c[u] * HD + lane * 4);
#pragma unroll
        for (int u = 0; u < 8; u++) {
            acc.x += vv[u] * xt[u].x; acc.y += vv[u] * xt[u].y;
            acc.z += vv[u] * xt[u].z; acc.w += vv[u] * xt[u].w;
        }
    }
    for (; j + 4 <= end; j += 4) {
        int c0 = g_ecol[j + 0], c1 = g_ecol[j + 1];
        int c2 = g_ecol[j + 2], c3 = g_ecol[j + 3];
        float v0 = g_mask[j + 0] * g_rs[c0], v1 = g_mask[j + 1] * g_rs[c1];
        float v2 = g_mask[j + 2] * g_rs[c2], v3 = g_mask[j + 3] * g_rs[c3];
        float4 x0 = *(const float4*)(x + (size_t)c0 * HD + lane * 4);
        float4 x1 = *(const float4*)(x + (size_t)c1 * HD + lane * 4);
        float4 x2 = *(const float4*)(x + (size_t)c2 * HD + lane * 4);
        float4 x3 = *(const float4*)(x + (size_t)c3 * HD + lane * 4);
        acc.x += v0 * x0.x; acc.y += v0 * x0.y; acc.z += v0 * x0.z; acc.w += v0 * x0.w;
        acc.x += v1 * x1.x; acc.y += v1 * x1.y; acc.z += v1 * x1.z; acc.w += v1 * x1.w;
        acc.x += v2 * x2.x; acc.y += v2 * x2.y; acc.z += v2 * x2.z; acc.w += v2 * x2.w;
        acc.x += v3 * x3.x; acc.y += v3 * x3.y; acc.z += v3 * x3.z; acc.w += v3 * x3.w;
    }
    for (; j < end; j++) {
        int c = g_ecol[j];
        float v = g_mask[j] * g_rs[c];
        float4 xc = *(const float4*)(x + (size_t)c * HD + lane * 4);
        acc.x += v * xc.x; acc.y += v * xc.y;
        acc.z += v * xc.z; acc.w += v * xc.w;
    }
    acc.x *= dr; acc.y *= dr; acc.z *= dr; acc.w *= dr;

    size_t o4 = (size_t)r * HD + lane * 4;
    *(float4*)(xo + o4) = acc;
    float4 base4 = first ? *(const float4*)(feat + o4) : *(const float4*)(out + o4);
    base4.x += acc.x; base4.y += acc.y; base4.z += acc.z; base4.w += acc.w;
    *(float4*)(out + o4) = base4;
}

// ---------------- launch ----------------
extern "C" void kernel_launch(void* const* d_in, const int* in_sizes, int n_in,
                              void* d_out, int out_size)
{
    const float* feat = (const float*)d_in[0];
    const float* nbW  = (const float*)d_in[1];
    const float* nbb  = (const float*)d_in[2];
    const float* sW   = (const float*)d_in[3];
    const float* sb   = (const float*)d_in[4];
    const float* a1W  = (const float*)d_in[5];
    const float* a1b  = (const float*)d_in[6];
    const float* a2W  = (const float*)d_in[7];
    const float* a2b  = (const float*)d_in[8];
    const int*   row  = (const int*)d_in[9];
    const int*   col  = (const int*)d_in[10];
    float* out = (float*)d_out;

    const int ggrid = (NN + 63) / 64;      // 1563
    const int rgrid = NN / 16;             // 6250
    const int ngrid = (NN + 255) / 256;
    const int egrid = (EE + 255) / 256;

    // gemm(l0) is independent of the CSR build — launch it first
    node_gemm<<<dim3(ggrid, 2), 256>>>(feat, 0,
                                       nbW, nbb, sW, sb, a1W);
    hist_k<<<egrid, 256>>>(row);
    scan1<<<NSCANBLK, SCANB>>>();
    scan23<<<ngrid, 256>>>();
    scatter_k<<<egrid, 256>>>(row, col);

    for (int l = 0; l < NLAY; l++) {
        int xsel = (l == 0) ? 0 : ((l == 1) ? 1 : 2);
        int useB = l & 1;
        if (l > 0) {
            node_gemm<<<dim3(ggrid, 2), 256>>>(feat, xsel,
                                               nbW + l * 4096, nbb + l * 64,
                                               sW  + l * 4096, sb  + l * 64,
                                               a1W + l * 8192);
        }
        edge_att_csr<<<rgrid, 256>>>(a1b + l * 64, a2W + l * 64, a2b + l);
        edge_spmm_csr<<<rgrid, 256>>>(feat, xsel, useB, out, l == 0);
    }
}